// round 2
// baseline (speedup 1.0000x reference)
#include <cuda_runtime.h>
#include <cstdint>

// Problem constants (from reference)
#define HID   4096
#define NEXP  4
#define RNK   8
#define LSCALE 1.0f      // ALPHA / RANK = 8/8
#define MAXN  16384

// Scratch (allocation-free rule: __device__ globals)
__device__ float g_zs[MAXN * RNK];     // pre-scaled z per token
__device__ int   g_top1[MAXN];         // routed expert per token

// ---------------------------------------------------------------------------
// Kernel A: per-token gating (argmax of logits) + LoRA z = A_e . x  (scaled)
// One block (128 threads) per token.
// ---------------------------------------------------------------------------
__global__ void gate_z_kernel(const float* __restrict__ x,
                              const float* __restrict__ gw,
                              const float* __restrict__ bias,
                              const float* __restrict__ lA) {
    const int n    = blockIdx.x;
    const int tid  = threadIdx.x;           // 128 threads
    const int wid  = tid >> 5;
    const int lane = tid & 31;

    const float4* xr = reinterpret_cast<const float4*>(x + (size_t)n * HID);
    __shared__ float sred[4][RNK];
    __shared__ int   s_e;

    // ---- Phase 1: logits for 4 experts ----
    float a[NEXP] = {0.f, 0.f, 0.f, 0.f};
    const float4* gw4 = reinterpret_cast<const float4*>(gw);
    for (int h = tid; h < HID / 4; h += 128) {
        float4 xv = xr[h];
#pragma unroll
        for (int e = 0; e < NEXP; e++) {
            float4 g = gw4[e * (HID / 4) + h];
            a[e] += xv.x * g.x + xv.y * g.y + xv.z * g.z + xv.w * g.w;
        }
    }
#pragma unroll
    for (int e = 0; e < NEXP; e++)
#pragma unroll
        for (int off = 16; off > 0; off >>= 1)
            a[e] += __shfl_xor_sync(0xffffffffu, a[e], off);
    if (lane == 0) {
#pragma unroll
        for (int e = 0; e < NEXP; e++) sred[wid][e] = a[e];
    }
    __syncthreads();
    if (tid == 0) {
        float best = -3.4e38f; int be = 0;
#pragma unroll
        for (int e = 0; e < NEXP; e++) {
            float v = sred[0][e] + sred[1][e] + sred[2][e] + sred[3][e] + bias[e];
            if (v > best) { best = v; be = e; }   // first-max tie break like argmax
        }
        s_e = be;
        g_top1[n] = be;
    }
    __syncthreads();

    // ---- Phase 2: z[r] = sum_h x[h] * A[e][r][h]  (x row re-read hits L1) ----
    const int e = s_e;
    const float4* A4 = reinterpret_cast<const float4*>(lA + (size_t)e * RNK * HID);
    float z[RNK];
#pragma unroll
    for (int r = 0; r < RNK; r++) z[r] = 0.f;
    for (int h = tid; h < HID / 4; h += 128) {
        float4 xv = xr[h];
#pragma unroll
        for (int r = 0; r < RNK; r++) {
            float4 g = A4[r * (HID / 4) + h];
            z[r] += xv.x * g.x + xv.y * g.y + xv.z * g.z + xv.w * g.w;
        }
    }
#pragma unroll
    for (int r = 0; r < RNK; r++)
#pragma unroll
        for (int off = 16; off > 0; off >>= 1)
            z[r] += __shfl_xor_sync(0xffffffffu, z[r], off);
    __syncthreads();   // sred re-use: make sure phase-1 reads are done
    if (lane == 0) {
#pragma unroll
        for (int r = 0; r < RNK; r++) sred[wid][r] = z[r];
    }
    __syncthreads();
    if (tid < RNK) {
        g_zs[(size_t)n * RNK + tid] =
            (sred[0][tid] + sred[1][tid] + sred[2][tid] + sred[3][tid]) * LSCALE;
    }
}

// ---------------------------------------------------------------------------
// Kernel B: out[n,o] = x[n,:] . W[o,:]  +  zs[n,:] . lora_B[e(n), o, :]
// Tiled fp32 GEMM, BM=BN=128, BK=16, 256 threads, 8x8 per thread,
// packed fma.rn.f32x2 (2x FFMA throughput vs 3-reg FFMA on sm_103a).
// ---------------------------------------------------------------------------
#define BM 128
#define BN 128
#define BK 16

__device__ __forceinline__ unsigned long long pk2(float lo, float hi) {
    unsigned long long r;
    asm("mov.b64 %0, {%1, %2};" : "=l"(r)
        : "r"(__float_as_uint(lo)), "r"(__float_as_uint(hi)));
    return r;
}
__device__ __forceinline__ void fma2(unsigned long long& c,
                                     unsigned long long a,
                                     unsigned long long b) {
    asm("fma.rn.f32x2 %0, %1, %2, %0;" : "+l"(c) : "l"(a), "l"(b));
}
__device__ __forceinline__ void upk2(unsigned long long v, float& lo, float& hi) {
    unsigned int u0, u1;
    asm("mov.b64 {%0, %1}, %2;" : "=r"(u0), "=r"(u1) : "l"(v));
    lo = __uint_as_float(u0);
    hi = __uint_as_float(u1);
}

__global__ __launch_bounds__(256)
void gemm_lora_kernel(const float* __restrict__ x,
                      const float* __restrict__ w,
                      const float* __restrict__ lB,
                      float* __restrict__ out) {
    __shared__ float As[BK][BM];
    __shared__ float Bs[BK][BN];

    const int tid = threadIdx.x;
    const int tx  = tid & 15;      // output-column direction (o)
    const int ty  = tid >> 4;      // output-row direction (n)
    const int m0  = blockIdx.y * BM;
    const int n0  = blockIdx.x * BN;

    // global-load assignment: 2 float4 per thread per operand
    const int lrow = tid >> 1;            // 0..127
    const int lk   = (tid & 1) * 8;       // 0 or 8
    const float* xg = x + (size_t)(m0 + lrow) * HID + lk;
    const float* wg = w + (size_t)(n0 + lrow) * HID + lk;

    unsigned long long c[8][4];
#pragma unroll
    for (int i = 0; i < 8; i++)
#pragma unroll
        for (int j = 0; j < 4; j++) c[i][j] = 0ull;

    // prefetch first tile
    float4 pxa = *(const float4*)(xg + 0);
    float4 pxb = *(const float4*)(xg + 4);
    float4 pwa = *(const float4*)(wg + 0);
    float4 pwb = *(const float4*)(wg + 4);

    for (int k0 = 0; k0 < HID; k0 += BK) {
        // stage prefetched tile into smem (transposed: As[k][m], Bs[k][o])
        As[lk + 0][lrow] = pxa.x; As[lk + 1][lrow] = pxa.y;
        As[lk + 2][lrow] = pxa.z; As[lk + 3][lrow] = pxa.w;
        As[lk + 4][lrow] = pxb.x; As[lk + 5][lrow] = pxb.y;
        As[lk + 6][lrow] = pxb.z; As[lk + 7][lrow] = pxb.w;
        Bs[lk + 0][lrow] = pwa.x; Bs[lk + 1][lrow] = pwa.y;
        Bs[lk + 2][lrow] = pwa.z; Bs[lk + 3][lrow] = pwa.w;
        Bs[lk + 4][lrow] = pwb.x; Bs[lk + 5][lrow] = pwb.y;
        Bs[lk + 6][lrow] = pwb.z; Bs[lk + 7][lrow] = pwb.w;
        __syncthreads();

        // prefetch next tile while computing this one
        if (k0 + BK < HID) {
            pxa = *(const float4*)(xg + k0 + BK);
            pxb = *(const float4*)(xg + k0 + BK + 4);
            pwa = *(const float4*)(wg + k0 + BK);
            pwb = *(const float4*)(wg + k0 + BK + 4);
        }

#pragma unroll
        for (int kk = 0; kk < BK; kk++) {
            float4 a0 = *(const float4*)&As[kk][ty * 8];
            float4 a1 = *(const float4*)&As[kk][ty * 8 + 4];
            float4 b0 = *(const float4*)&Bs[kk][tx * 8];
            float4 b1 = *(const float4*)&Bs[kk][tx * 8 + 4];
            unsigned long long bb[4];
            bb[0] = pk2(b0.x, b0.y); bb[1] = pk2(b0.z, b0.w);
            bb[2] = pk2(b1.x, b1.y); bb[3] = pk2(b1.z, b1.w);
            float av[8] = {a0.x, a0.y, a0.z, a0.w, a1.x, a1.y, a1.z, a1.w};
#pragma unroll
            for (int i = 0; i < 8; i++) {
                unsigned long long aa = pk2(av[i], av[i]);
                fma2(c[i][0], aa, bb[0]);
                fma2(c[i][1], aa, bb[1]);
                fma2(c[i][2], aa, bb[2]);
                fma2(c[i][3], aa, bb[3]);
            }
        }
        __syncthreads();
    }

    // ---- epilogue: add LoRA delta, write out ----
#pragma unroll
    for (int i = 0; i < 8; i++) {
        const int row = m0 + ty * 8 + i;
        const int e   = g_top1[row];
        const float4* zs4 = reinterpret_cast<const float4*>(g_zs + (size_t)row * RNK);
        float4 z0 = zs4[0], z1 = zs4[1];
        const float* lbe  = lB + (size_t)e * HID * RNK;
        float* orow = out + (size_t)row * HID + n0 + tx * 8;
#pragma unroll
        for (int j = 0; j < 4; j++) {
            const int o0 = n0 + tx * 8 + 2 * j;
            const float4* p4 = reinterpret_cast<const float4*>(lbe + (size_t)o0 * RNK);
            float4 p0 = p4[0], p1 = p4[1];
            const float4* q4 = reinterpret_cast<const float4*>(lbe + (size_t)(o0 + 1) * RNK);
            float4 q0 = q4[0], q1 = q4[1];
            float d0 = z0.x * p0.x + z0.y * p0.y + z0.z * p0.z + z0.w * p0.w
                     + z1.x * p1.x + z1.y * p1.y + z1.z * p1.z + z1.w * p1.w;
            float d1 = z0.x * q0.x + z0.y * q0.y + z0.z * q0.z + z0.w * q0.w
                     + z1.x * q1.x + z1.y * q1.y + z1.z * q1.z + z1.w * q1.w;
            float clo, chi;
            upk2(c[i][j], clo, chi);
            float2 res = make_float2(clo + d0, chi + d1);
            *reinterpret_cast<float2*>(orow + 2 * j) = res;
        }
    }
}

// ---------------------------------------------------------------------------
extern "C" void kernel_launch(void* const* d_in, const int* in_sizes, int n_in,
                              void* d_out, int out_size) {
    const float* x    = (const float*)d_in[0];  // [B,T,H] fp32
    const float* W_up = (const float*)d_in[1];  // [H,H]   (o,h)
    const float* gw   = (const float*)d_in[2];  // [E,H]
    const float* bias = (const float*)d_in[3];  // [E]
    const float* lA   = (const float*)d_in[4];  // [E,R,H]
    const float* lBm  = (const float*)d_in[5];  // [E,H,R]
    float* out        = (float*)d_out;          // [B,T,H]

    const int N = in_sizes[0] / HID;            // 16384 tokens

    gate_z_kernel<<<N, 128>>>(x, gw, bias, lA);

    dim3 grid(HID / BN, N / BM);                // (32, 128)
    gemm_lora_kernel<<<grid, 256>>>(x, W_up, lBm, out);
}

// round 4
// speedup vs baseline: 3.3923x; 3.3923x over previous
#include <cuda_runtime.h>
#include <cstdint>

// ---------------- problem constants ----------------
#define HID   4096
#define NEXP  4
#define RNK   8
#define MAXN  16384

// ---------------- GEMM tiling ----------------
#define BM 128
#define BN 128
#define BK 32
#define NCHUNK (HID / BK)            // 128
#define ROWB   144                    // 32 floats + 4 pad = 144 bytes/row
#define A_STAGE (BM * ROWB)           // 18432
#define STAGE_BYTES (2 * A_STAGE)     // 36864 (A then B)
#define STAGES 3
#define DYN_SMEM (STAGES * STAGE_BYTES)   // 110592

// scratch (allocation-free rule)
__device__ float g_zs[MAXN * RNK];
__device__ int   g_top1[MAXN];

// ---------------- PTX helpers ----------------
__device__ __forceinline__ uint32_t smem_u32(const void* p) {
    uint32_t a;
    asm("{ .reg .u64 t; cvta.to.shared.u64 t, %1; cvt.u32.u64 %0, t; }"
        : "=r"(a) : "l"(p));
    return a;
}
__device__ __forceinline__ void cp_async16(uint32_t dst, const void* src) {
    asm volatile("cp.async.cg.shared.global [%0], [%1], 16;"
                 :: "r"(dst), "l"(src) : "memory");
}
#define CP_COMMIT() asm volatile("cp.async.commit_group;" ::: "memory")
#define CP_WAIT2()  asm volatile("cp.async.wait_group 2;"  ::: "memory")

__device__ __forceinline__ void ldsm4(uint32_t* d, uint32_t addr) {
    asm volatile("ldmatrix.sync.aligned.m8n8.x4.shared.b16 {%0,%1,%2,%3}, [%4];"
                 : "=r"(d[0]), "=r"(d[1]), "=r"(d[2]), "=r"(d[3]) : "r"(addr));
}
__device__ __forceinline__ uint32_t f2tf(uint32_t x) {
    uint32_t y;
    asm("cvt.rna.tf32.f32 %0, %1;" : "=r"(y) : "r"(x));
    return y;
}
__device__ __forceinline__ void mma_tf32(float* c, const uint32_t* a,
                                         uint32_t b0, uint32_t b1) {
    asm volatile(
        "mma.sync.aligned.m16n8k8.row.col.f32.tf32.tf32.f32 "
        "{%0,%1,%2,%3},{%4,%5,%6,%7},{%8,%9},{%0,%1,%2,%3};"
        : "+f"(c[0]), "+f"(c[1]), "+f"(c[2]), "+f"(c[3])
        : "r"(a[0]), "r"(a[1]), "r"(a[2]), "r"(a[3]), "r"(b0), "r"(b1));
}

// ---------------------------------------------------------------------------
// Kernel A: per-token gating + LoRA z = A_e . x
// ---------------------------------------------------------------------------
__global__ void gate_z_kernel(const float* __restrict__ x,
                              const float* __restrict__ gw,
                              const float* __restrict__ bias,
                              const float* __restrict__ lA) {
    const int n    = blockIdx.x;
    const int tid  = threadIdx.x;
    const int wid  = tid >> 5;
    const int lane = tid & 31;

    const float4* xr = reinterpret_cast<const float4*>(x + (size_t)n * HID);
    __shared__ float sred[4][RNK];
    __shared__ int   s_e;

    float a[NEXP] = {0.f, 0.f, 0.f, 0.f};
    const float4* gw4 = reinterpret_cast<const float4*>(gw);
    for (int h = tid; h < HID / 4; h += 128) {
        float4 xv = xr[h];
#pragma unroll
        for (int e = 0; e < NEXP; e++) {
            float4 g = gw4[e * (HID / 4) + h];
            a[e] += xv.x * g.x + xv.y * g.y + xv.z * g.z + xv.w * g.w;
        }
    }
#pragma unroll
    for (int e = 0; e < NEXP; e++)
#pragma unroll
        for (int off = 16; off > 0; off >>= 1)
            a[e] += __shfl_xor_sync(0xffffffffu, a[e], off);
    if (lane == 0)
#pragma unroll
        for (int e = 0; e < NEXP; e++) sred[wid][e] = a[e];
    __syncthreads();
    if (tid == 0) {
        float best = -3.4e38f; int be = 0;
#pragma unroll
        for (int e = 0; e < NEXP; e++) {
            float v = sred[0][e] + sred[1][e] + sred[2][e] + sred[3][e] + bias[e];
            if (v > best) { best = v; be = e; }
        }
        s_e = be;
        g_top1[n] = be;
    }
    __syncthreads();

    const int e = s_e;
    const float4* A4 = reinterpret_cast<const float4*>(lA + (size_t)e * RNK * HID);
    float z[RNK];
#pragma unroll
    for (int r = 0; r < RNK; r++) z[r] = 0.f;
    for (int h = tid; h < HID / 4; h += 128) {
        float4 xv = xr[h];
#pragma unroll
        for (int r = 0; r < RNK; r++) {
            float4 g = A4[r * (HID / 4) + h];
            z[r] += xv.x * g.x + xv.y * g.y + xv.z * g.z + xv.w * g.w;
        }
    }
#pragma unroll
    for (int r = 0; r < RNK; r++)
#pragma unroll
        for (int off = 16; off > 0; off >>= 1)
            z[r] += __shfl_xor_sync(0xffffffffu, z[r], off);
    __syncthreads();
    if (lane == 0)
#pragma unroll
        for (int r = 0; r < RNK; r++) sred[wid][r] = z[r];
    __syncthreads();
    if (tid < RNK)
        g_zs[(size_t)n * RNK + tid] =
            sred[0][tid] + sred[1][tid] + sred[2][tid] + sred[3][tid];
}

// ---------------------------------------------------------------------------
// Kernel B: tf32 mma.sync GEMM + fused LoRA epilogue
// 256 threads, CTA tile 128x128x32, warp tile 64x32, 3-stage cp.async.
// ---------------------------------------------------------------------------
__device__ __forceinline__ void load_chunk(uint32_t base,
                                           const float* __restrict__ x,
                                           const float* __restrict__ w,
                                           int m0, int n0, int k0, int tid) {
    const int seg = tid & 7;       // 16B segment in 128B row
    const int r0  = tid >> 3;      // 0..31
    const float* ga = x + (size_t)(m0 + r0) * HID + k0 + seg * 4;
    const float* gb = w + (size_t)(n0 + r0) * HID + k0 + seg * 4;
#pragma unroll
    for (int i = 0; i < 4; i++) {
        const uint32_t off = (uint32_t)(r0 + i * 32) * ROWB + seg * 16;
        cp_async16(base + off,           ga + (size_t)i * 32 * HID);
        cp_async16(base + A_STAGE + off, gb + (size_t)i * 32 * HID);
    }
}

__global__ __launch_bounds__(256)
void mma_gemm_kernel(const float* __restrict__ x,
                     const float* __restrict__ w,
                     const float* __restrict__ lB,
                     float* __restrict__ out) {
    extern __shared__ __align__(16) char dsm[];
    const uint32_t tiles = smem_u32(dsm);

    const int tid  = threadIdx.x;
    const int wid  = tid >> 5;
    const int lane = tid & 31;
    const int wm   = (wid & 1) * 64;     // warp m offset in CTA tile
    const int wn   = (wid >> 1) * 32;    // warp n offset
    const int m0   = blockIdx.y * BM;
    const int n0   = blockIdx.x * BN;

    // ldmatrix per-lane address offsets
    const int q = lane >> 3, r = lane & 7;
    uint32_t aoff[4], boff[4];
#pragma unroll
    for (int mt = 0; mt < 4; mt++)
        aoff[mt] = (uint32_t)(wm + mt * 16 + (q & 1) * 8 + r) * ROWB + (q >> 1) * 16;
#pragma unroll
    for (int nt = 0; nt < 4; nt++)
        boff[nt] = (uint32_t)(wn + nt * 8 + r) * ROWB + q * 16;

    float c[4][4][4];
#pragma unroll
    for (int i = 0; i < 4; i++)
#pragma unroll
        for (int j = 0; j < 4; j++)
#pragma unroll
            for (int t = 0; t < 4; t++) c[i][j][t] = 0.f;

    // prologue: stages 0, 1
    load_chunk(tiles + 0 * STAGE_BYTES, x, w, m0, n0, 0 * BK, tid);
    CP_COMMIT();
    load_chunk(tiles + 1 * STAGE_BYTES, x, w, m0, n0, 1 * BK, tid);
    CP_COMMIT();

    for (int k = 0; k < NCHUNK; k++) {
        if (k + 2 < NCHUNK)
            load_chunk(tiles + ((k + 2) % STAGES) * STAGE_BYTES,
                       x, w, m0, n0, (k + 2) * BK, tid);
        CP_COMMIT();           // empty groups at tail keep wait positional
        CP_WAIT2();            // chunk k resident
        __syncthreads();

        const uint32_t sA = tiles + (k % STAGES) * STAGE_BYTES;
        const uint32_t sB = sA + A_STAGE;

#pragma unroll
        for (int j = 0; j < 2; j++) {            // k-step pairs
            uint32_t Bf[4][4];
#pragma unroll
            for (int nt = 0; nt < 4; nt++) {
                ldsm4(Bf[nt], sB + boff[nt] + j * 64);
#pragma unroll
                for (int t = 0; t < 4; t++) Bf[nt][t] = f2tf(Bf[nt][t]);
            }
#pragma unroll
            for (int half = 0; half < 2; half++) {
                uint32_t Af[4][4];
#pragma unroll
                for (int mt = 0; mt < 4; mt++) {
                    ldsm4(Af[mt], sA + aoff[mt] + (2 * j + half) * 32);
#pragma unroll
                    for (int t = 0; t < 4; t++) Af[mt][t] = f2tf(Af[mt][t]);
                }
#pragma unroll
                for (int mt = 0; mt < 4; mt++)
#pragma unroll
                    for (int nt = 0; nt < 4; nt++)
                        mma_tf32(c[mt][nt], Af[mt],
                                 Bf[nt][2 * half], Bf[nt][2 * half + 1]);
            }
        }
        __syncthreads();       // stage k%3 is refilled next iteration
    }

    // ---- epilogue: add LoRA delta, write out ----
    const int rowg = lane >> 2;          // 0..7
    const int colg = (lane & 3) * 2;
#pragma unroll
    for (int mt = 0; mt < 4; mt++) {
#pragma unroll
        for (int hr = 0; hr < 2; hr++) {
            const int row = m0 + wm + mt * 16 + hr * 8 + rowg;
            const int e   = g_top1[row];
            const float4* zz = reinterpret_cast<const float4*>(g_zs + (size_t)row * RNK);
            const float4 z0 = zz[0], z1 = zz[1];
            const float* lbe = lB + (size_t)e * HID * RNK;
            float* orow = out + (size_t)row * HID;
#pragma unroll
            for (int nt = 0; nt < 4; nt++) {
                const int col = n0 + wn + nt * 8 + colg;
                const float4* bp =
                    reinterpret_cast<const float4*>(lbe + (size_t)col * RNK);
                const float4 b0 = bp[0], b1 = bp[1];
                const float4* bq =
                    reinterpret_cast<const float4*>(lbe + (size_t)(col + 1) * RNK);
                const float4 q0 = bq[0], q1 = bq[1];
                float d0 = z0.x * b0.x + z0.y * b0.y + z0.z * b0.z + z0.w * b0.w
                         + z1.x * b1.x + z1.y * b1.y + z1.z * b1.z + z1.w * b1.w;
                float d1 = z0.x * q0.x + z0.y * q0.y + z0.z * q0.z + z0.w * q0.w
                         + z1.x * q1.x + z1.y * q1.y + z1.z * q1.z + z1.w * q1.w;
                float2 res = make_float2(c[mt][nt][hr * 2 + 0] + d0,
                                         c[mt][nt][hr * 2 + 1] + d1);
                *reinterpret_cast<float2*>(orow + col) = res;
            }
        }
    }
}

// ---------------------------------------------------------------------------
extern "C" void kernel_launch(void* const* d_in, const int* in_sizes, int n_in,
                              void* d_out, int out_size) {
    const float* x    = (const float*)d_in[0];
    const float* W_up = (const float*)d_in[1];
    const float* gw   = (const float*)d_in[2];
    const float* bias = (const float*)d_in[3];
    const float* lA   = (const float*)d_in[4];
    const float* lBm  = (const float*)d_in[5];
    float* out        = (float*)d_out;

    const int N = in_sizes[0] / HID;   // 16384 tokens

    cudaFuncSetAttribute(mma_gemm_kernel,
                         cudaFuncAttributeMaxDynamicSharedMemorySize, DYN_SMEM);

    gate_z_kernel<<<N, 128>>>(x, gw, bias, lA);

    dim3 grid(HID / BN, N / BM);       // (32, 128)
    mma_gemm_kernel<<<grid, 256, DYN_SMEM>>>(x, W_up, lBm, out);
}